// round 1
// baseline (speedup 1.0000x reference)
#include <cuda_runtime.h>
#include <cstdint>

#define B_    256
#define T_    512
#define D_    256
#define K_    256
#define BT_   (B_ * T_)

// 128 MiB scratch for the precomputed input projection xU[B*T, K]
__device__ float g_xU[(size_t)BT_ * K_];

// ---------------------------------------------------------------------------
// Phase A: g_xU[m, n] = sum_k X[m, k] * U[k, n] + bias[n]
// 128x128 tile, BK=8, 256 threads, 8x8 per-thread microtile.
// ---------------------------------------------------------------------------
__global__ __launch_bounds__(256) void xu_gemm(const float* __restrict__ X,
                                               const float* __restrict__ U,
                                               const float* __restrict__ bias) {
    __shared__ float As[8][128];   // transposed X tile: As[k][m]
    __shared__ float Bs[8][128];   // U tile: Bs[k][n]

    const int tid  = threadIdx.x;
    const int mblk = blockIdx.x * 128;
    const int nblk = blockIdx.y * 128;

    const int aRow = tid >> 1;         // 0..127
    const int aCol = (tid & 1) * 4;    // 0 or 4
    const int bRow = tid >> 5;         // 0..7
    const int bCol = (tid & 31) * 4;   // 0..124

    const int ty = tid >> 4;           // 0..15
    const int tx = tid & 15;           // 0..15

    const float* Xp = X + (size_t)(mblk + aRow) * D_ + aCol;
    const float* Up = U + (size_t)bRow * K_ + nblk + bCol;

    float acc[8][8];
#pragma unroll
    for (int i = 0; i < 8; i++)
#pragma unroll
        for (int j = 0; j < 8; j++) acc[i][j] = 0.0f;

    for (int k0 = 0; k0 < D_; k0 += 8) {
        float4 a4 = *(const float4*)(Xp + k0);
        float4 b4 = *(const float4*)(Up + (size_t)k0 * K_);
        __syncthreads();
        As[aCol + 0][aRow] = a4.x;
        As[aCol + 1][aRow] = a4.y;
        As[aCol + 2][aRow] = a4.z;
        As[aCol + 3][aRow] = a4.w;
        *(float4*)(&Bs[bRow][bCol]) = b4;
        __syncthreads();
#pragma unroll
        for (int kk = 0; kk < 8; kk++) {
            float a[8], b[8];
            *(float4*)(a)     = *(const float4*)(&As[kk][ty * 8]);
            *(float4*)(a + 4) = *(const float4*)(&As[kk][ty * 8 + 4]);
            *(float4*)(b)     = *(const float4*)(&Bs[kk][tx * 8]);
            *(float4*)(b + 4) = *(const float4*)(&Bs[kk][tx * 8 + 4]);
#pragma unroll
            for (int i = 0; i < 8; i++)
#pragma unroll
                for (int j = 0; j < 8; j++)
                    acc[i][j] = fmaf(a[i], b[j], acc[i][j]);
        }
    }

    // epilogue: + bias, store
#pragma unroll
    for (int i = 0; i < 8; i++) {
        const size_t row = (size_t)(mblk + ty * 8 + i);
        float* Cp = g_xU + row * K_ + nblk + tx * 8;
#pragma unroll
        for (int j = 0; j < 8; j += 4) {
            float4 v;
            v.x = acc[i][j + 0] + bias[nblk + tx * 8 + j + 0];
            v.y = acc[i][j + 1] + bias[nblk + tx * 8 + j + 1];
            v.z = acc[i][j + 2] + bias[nblk + tx * 8 + j + 2];
            v.w = acc[i][j + 3] + bias[nblk + tx * 8 + j + 3];
            *(float4*)(Cp + j) = v;
        }
    }
}

// ---------------------------------------------------------------------------
// Phase B: recurrence. 64 clusters of 2 CTAs; each cluster owns 4 batch rows.
// CTA rank r holds W columns [r*128, r*128+128) in smem (fp32, 128 KB).
// h (4 rows x 256) double-buffered in each CTA's smem; each step the CTA
// computes its column half and pushes it to the peer via st.shared::cluster.
// One barrier.cluster per step.
// ---------------------------------------------------------------------------
__global__ void __cluster_dims__(2, 1, 1) __launch_bounds__(256, 1)
rnn_scan(const float* __restrict__ W, float* __restrict__ out) {
    extern __shared__ float sm[];
    float* ws  = sm;                   // 32768 floats: ws[d*128 + c], d=0..255, c=0..127 (this CTA's col half)
    float* hs  = sm + 32768;           // 2 * 1024 floats: hs[buf*1024 + d*4 + r]
    float* red = sm + 32768 + 2048;    // 512 floats: partial sums from dh==1 threads

    const int tid = threadIdx.x;
    const int c   = tid & 127;         // column within this CTA's half
    const int dh  = tid >> 7;          // 0/1: which half of the d-range this thread sums

    uint32_t rank;
    asm("mov.u32 %0, %%cluster_ctarank;" : "=r"(rank));
    const uint32_t peer = rank ^ 1u;
    const int b0 = (blockIdx.x >> 1) * 4;   // first batch row of this cluster

    // load this CTA's W column-half into smem
    {
        const float* Wg = W + rank * 128;
        for (int i = tid * 4; i < 32768; i += 1024) {
            const int d  = i >> 7;
            const int cc = i & 127;
            *(float4*)(ws + i) = *(const float4*)(Wg + (size_t)d * K_ + cc);
        }
    }
    // zero both h buffers (h0 = 0)
    for (int i = tid; i < 2048; i += 256) hs[i] = 0.0f;
    __syncthreads();
    asm volatile("barrier.cluster.arrive.aligned;" ::: "memory");
    asm volatile("barrier.cluster.wait.aligned;" ::: "memory");

    // peer hs base address (mapa once)
    uint32_t hs_u32;
    asm("{ .reg .u64 t0; cvta.to.shared.u64 t0, %1; cvt.u32.u64 %0, t0; }"
        : "=r"(hs_u32) : "l"(hs));
    uint32_t hs_peer;
    asm("mapa.shared::cluster.u32 %0, %1, %2;" : "=r"(hs_peer) : "r"(hs_u32), "r"(peer));

    const int myd = (int)rank * 128 + c;   // hidden index this thread produces (dh==0 lanes)
    const float* xbase = g_xU + (size_t)b0 * (T_ * K_) + rank * 128 + c;

    for (int t = 0; t < T_; t++) {
        // prefetch this step's xU values (only needed after the d-loop;
        // DRAM latency hides under ~2000 cycles of FMA)
        float xu0 = 0.f, xu1 = 0.f, xu2 = 0.f, xu3 = 0.f;
        if (dh == 0) {
            const float* xp = xbase + (size_t)t * K_;
            xu0 = xp[0];
            xu1 = xp[(size_t)1 * T_ * K_];
            xu2 = xp[(size_t)2 * T_ * K_];
            xu3 = xp[(size_t)3 * T_ * K_];
        }

        float acc0 = 0.f, acc1 = 0.f, acc2 = 0.f, acc3 = 0.f;
        const float* hb = hs + (t & 1) * 1024 + dh * 512;   // h[d][0..3], d from dh*128
        const float* wp = ws + dh * 16384 + c;              // ws[d*128 + c]
#pragma unroll 16
        for (int dd = 0; dd < 128; dd++) {
            const float4 h4 = *(const float4*)(hb + dd * 4);  // broadcast
            const float  w  = wp[dd * 128];                    // coalesced across c
            acc0 = fmaf(h4.x, w, acc0);
            acc1 = fmaf(h4.y, w, acc1);
            acc2 = fmaf(h4.z, w, acc2);
            acc3 = fmaf(h4.w, w, acc3);
        }

        if (dh == 1) *(float4*)(red + c * 4) = make_float4(acc0, acc1, acc2, acc3);
        __syncthreads();

        if (dh == 0) {
            const float4 p = *(const float4*)(red + c * 4);
            const float v0 = tanhf(acc0 + p.x + xu0);
            const float v1 = tanhf(acc1 + p.y + xu1);
            const float v2 = tanhf(acc2 + p.z + xu2);
            const float v3 = tanhf(acc3 + p.w + xu3);

            const int wb = ((t + 1) & 1) * 1024 + myd * 4;    // float index
            *(float4*)(hs + wb) = make_float4(v0, v1, v2, v3);

            const uint32_t raddr = hs_peer + (uint32_t)wb * 4u;
            asm volatile("st.shared::cluster.f32 [%0], %1;"      :: "r"(raddr),        "f"(v0) : "memory");
            asm volatile("st.shared::cluster.f32 [%0], %1;"      :: "r"(raddr + 4u),   "f"(v1) : "memory");
            asm volatile("st.shared::cluster.f32 [%0], %1;"      :: "r"(raddr + 8u),   "f"(v2) : "memory");
            asm volatile("st.shared::cluster.f32 [%0], %1;"      :: "r"(raddr + 12u),  "f"(v3) : "memory");

            if (t == T_ - 1) {
                out[(size_t)(b0 + 0) * K_ + myd] = v0;
                out[(size_t)(b0 + 1) * K_ + myd] = v1;
                out[(size_t)(b0 + 2) * K_ + myd] = v2;
                out[(size_t)(b0 + 3) * K_ + myd] = v3;
            }
        }

        // release own+peer writes; acquire peer's writes for next step
        asm volatile("barrier.cluster.arrive.aligned;" ::: "memory");
        asm volatile("barrier.cluster.wait.aligned;"   ::: "memory");
    }
}

// ---------------------------------------------------------------------------
extern "C" void kernel_launch(void* const* d_in, const int* in_sizes, int n_in,
                              void* d_out, int out_size) {
    const float* X    = (const float*)d_in[0];  // [B,T,D]
    const float* U    = (const float*)d_in[1];  // [D,K]
    const float* W    = (const float*)d_in[2];  // [K,K]
    const float* bias = (const float*)d_in[3];  // [K]
    float* out = (float*)d_out;                 // [B,1,K]

    // Phase A: xU = X @ U + b
    dim3 g1(BT_ / 128, K_ / 128);
    xu_gemm<<<g1, 256>>>(X, U, bias);

    // Phase B: persistent cluster recurrence
    const int smemB = (32768 + 2048 + 512) * (int)sizeof(float);  // 141312 B
    cudaFuncSetAttribute(rnn_scan, cudaFuncAttributeMaxDynamicSharedMemorySize, smemB);
    rnn_scan<<<128, 256, smemB>>>(W, out);
}

// round 2
// speedup vs baseline: 1.3710x; 1.3710x over previous
#include <cuda_runtime.h>
#include <cstdint>

#define B_    256
#define T_    512
#define D_    256
#define K_    256
#define BT_   (B_ * T_)

// 128 MiB scratch for the precomputed input projection xU[B*T, K]
__device__ float g_xU[(size_t)BT_ * K_];

// ---------------- packed f32x2 helpers (sm_103a FFMA2) ----------------------
__device__ __forceinline__ uint64_t pk2(float x, float y) {
    uint64_t r; asm("mov.b64 %0, {%1, %2};" : "=l"(r) : "f"(x), "f"(y)); return r;
}
__device__ __forceinline__ void upk2(uint64_t v, float& x, float& y) {
    asm("mov.b64 {%0, %1}, %2;" : "=f"(x), "=f"(y) : "l"(v));
}
__device__ __forceinline__ uint64_t ffma2(uint64_t a, uint64_t b, uint64_t c) {
    uint64_t d; asm("fma.rn.f32x2 %0, %1, %2, %3;" : "=l"(d) : "l"(a), "l"(b), "l"(c)); return d;
}
__device__ __forceinline__ uint64_t fadd2(uint64_t a, uint64_t b) {
    uint64_t d; asm("add.rn.f32x2 %0, %1, %2;" : "=l"(d) : "l"(a), "l"(b)); return d;
}
__device__ __forceinline__ void lds_v2u64(uint32_t addr, uint64_t& a, uint64_t& b) {
    asm volatile("ld.shared.v2.u64 {%0, %1}, [%2];" : "=l"(a), "=l"(b) : "r"(addr));
}
__device__ __forceinline__ uint32_t smem_u32(const void* p) {
    return (uint32_t)__cvta_generic_to_shared(p);
}

// ---------------------------------------------------------------------------
// Phase A: g_xU[m, n] = sum_k X[m, k] * U[k, n] + bias[n]
// 128x128 tile, BK=8, 256 threads, 8x8 per-thread microtile, FFMA2 core.
// ---------------------------------------------------------------------------
__global__ __launch_bounds__(256) void xu_gemm(const float* __restrict__ X,
                                               const float* __restrict__ U,
                                               const float* __restrict__ bias) {
    __shared__ float As[8][128];   // transposed X tile: As[k][m]
    __shared__ float Bs[8][128];   // U tile: Bs[k][n]

    const int tid  = threadIdx.x;
    const int mblk = blockIdx.x * 128;
    const int nblk = blockIdx.y * 128;

    const int aRow = tid >> 1;         // 0..127
    const int aCol = (tid & 1) * 4;    // 0 or 4
    const int bRow = tid >> 5;         // 0..7
    const int bCol = (tid & 31) * 4;   // 0..124

    const int ty = tid >> 4;           // 0..15
    const int tx = tid & 15;           // 0..15

    const float* Xp = X + (size_t)(mblk + aRow) * D_ + aCol;
    const float* Up = U + (size_t)bRow * K_ + nblk + bCol;

    const uint32_t as_base = smem_u32(&As[0][0]);
    const uint32_t bs_base = smem_u32(&Bs[0][0]);

    uint64_t acc2[8][4];               // acc2[i][jp] = cols (2jp, 2jp+1) of row i
    const uint64_t z2 = pk2(0.0f, 0.0f);
#pragma unroll
    for (int i = 0; i < 8; i++)
#pragma unroll
        for (int j = 0; j < 4; j++) acc2[i][j] = z2;

    for (int k0 = 0; k0 < D_; k0 += 8) {
        float4 a4 = *(const float4*)(Xp + k0);
        float4 b4 = *(const float4*)(Up + (size_t)k0 * K_);
        __syncthreads();
        As[aCol + 0][aRow] = a4.x;
        As[aCol + 1][aRow] = a4.y;
        As[aCol + 2][aRow] = a4.z;
        As[aCol + 3][aRow] = a4.w;
        *(float4*)(&Bs[bRow][bCol]) = b4;
        __syncthreads();
#pragma unroll
        for (int kk = 0; kk < 8; kk++) {
            float a[8];
            *(float4*)(a)     = *(const float4*)(&As[kk][ty * 8]);
            *(float4*)(a + 4) = *(const float4*)(&As[kk][ty * 8 + 4]);
            uint64_t bp[4];
            const uint32_t baddr = bs_base + (uint32_t)(kk * 128 + tx * 8) * 4u;
            lds_v2u64(baddr,       bp[0], bp[1]);
            lds_v2u64(baddr + 16u, bp[2], bp[3]);
#pragma unroll
            for (int i = 0; i < 8; i++) {
                const uint64_t ap = pk2(a[i], a[i]);
#pragma unroll
                for (int jp = 0; jp < 4; jp++)
                    acc2[i][jp] = ffma2(ap, bp[jp], acc2[i][jp]);
            }
        }
    }

    // epilogue: + bias, store
    float bvals[8];
#pragma unroll
    for (int j = 0; j < 8; j++) bvals[j] = bias[nblk + tx * 8 + j];
#pragma unroll
    for (int i = 0; i < 8; i++) {
        const size_t row = (size_t)(mblk + ty * 8 + i);
        float* Cp = g_xU + row * K_ + nblk + tx * 8;
        float v[8];
#pragma unroll
        for (int jp = 0; jp < 4; jp++) upk2(acc2[i][jp], v[2 * jp], v[2 * jp + 1]);
#pragma unroll
        for (int j = 0; j < 8; j += 4) {
            float4 o;
            o.x = v[j + 0] + bvals[j + 0];
            o.y = v[j + 1] + bvals[j + 1];
            o.z = v[j + 2] + bvals[j + 2];
            o.w = v[j + 3] + bvals[j + 3];
            *(float4*)(Cp + j) = o;
        }
    }
}

// ---------------------------------------------------------------------------
// Phase B: recurrence. 64 clusters of 2 CTAs; each cluster owns 4 batch rows.
// W lives in REGISTERS: thread (c, dh) holds W[dh*128 + j][rank*128 + c] for
// j in [0,128). h (4 rows x 256) double-buffered in smem; inner loop is
// 1x LDS.128 (two row-pairs) + 1 MOV (dup w) + 2 FFMA2 per hidden index.
// Cluster barrier split into arrive / wait with xU prefetch in between.
// ---------------------------------------------------------------------------
__global__ void __cluster_dims__(2, 1, 1) __launch_bounds__(256, 1)
rnn_scan(const float* __restrict__ W, float* __restrict__ out) {
    __shared__ float    hs[2][256 * 4];    // hs[buf][d*4 + r]
    __shared__ uint64_t red[128][2];       // partial sums from dh==1 threads

    const int tid = threadIdx.x;
    const int c   = tid & 127;         // column within this CTA's half
    const int dh  = tid >> 7;          // 0/1: which half of the d-range this thread sums

    uint32_t rank;
    asm("mov.u32 %0, %%cluster_ctarank;" : "=r"(rank));
    const uint32_t peer = rank ^ 1u;
    const int b0 = (blockIdx.x >> 1) * 4;   // first batch row of this cluster
    const int myd = (int)rank * 128 + c;    // hidden index this thread produces

    // ---- load this thread's W column slice into registers ----
    float w[128];
    {
        const float* Wg = W + (size_t)(dh * 128) * K_ + myd;
#pragma unroll
        for (int j = 0; j < 128; j++) w[j] = Wg[(size_t)j * K_];
    }

    // zero both h buffers (h0 = 0)
    for (int i = tid; i < 2048; i += 256) ((float*)hs)[i] = 0.0f;
    __syncthreads();
    asm volatile("barrier.cluster.arrive.aligned;" ::: "memory");
    asm volatile("barrier.cluster.wait.aligned;"   ::: "memory");

    // peer hs base address (mapa once)
    const uint32_t hs_local = smem_u32(&hs[0][0]);
    uint32_t hs_peer;
    asm("mapa.shared::cluster.u32 %0, %1, %2;" : "=r"(hs_peer) : "r"(hs_local), "r"(peer));
    const uint32_t red_base = smem_u32(&red[0][0]);

    const float* xbase = g_xU + (size_t)b0 * (T_ * K_) + myd;

    // prefetch xU for step 0
    float xu0 = 0.f, xu1 = 0.f, xu2 = 0.f, xu3 = 0.f;
    if (dh == 0) {
        xu0 = xbase[0];
        xu1 = xbase[(size_t)1 * T_ * K_];
        xu2 = xbase[(size_t)2 * T_ * K_];
        xu3 = xbase[(size_t)3 * T_ * K_];
    }

    for (int t = 0; t < T_; t++) {
        // ---- matvec over this thread's d-half ----
        uint64_t acc01 = pk2(0.f, 0.f);
        uint64_t acc23 = pk2(0.f, 0.f);
        const uint32_t hb = hs_local + (uint32_t)((t & 1) * 1024 + dh * 512) * 4u;
#pragma unroll
        for (int j = 0; j < 128; j++) {
            uint64_t h01, h23;
            lds_v2u64(hb + (uint32_t)j * 16u, h01, h23);   // rows (0,1) and (2,3) of hidden d
            const uint64_t wp = pk2(w[j], w[j]);
            acc01 = ffma2(h01, wp, acc01);
            acc23 = ffma2(h23, wp, acc23);
        }

        if (dh == 1) {
            asm volatile("st.shared.v2.u64 [%0], {%1, %2};"
                         :: "r"(red_base + (uint32_t)c * 16u), "l"(acc01), "l"(acc23) : "memory");
        }
        __syncthreads();

        if (dh == 0) {
            uint64_t p01, p23;
            lds_v2u64(red_base + (uint32_t)c * 16u, p01, p23);
            acc01 = fadd2(acc01, p01);
            acc23 = fadd2(acc23, p23);
            float a0, a1, a2, a3;
            upk2(acc01, a0, a1);
            upk2(acc23, a2, a3);
            const float v0 = tanhf(a0 + xu0);
            const float v1 = tanhf(a1 + xu1);
            const float v2 = tanhf(a2 + xu2);
            const float v3 = tanhf(a3 + xu3);

            const uint32_t wb = (uint32_t)(((t + 1) & 1) * 1024 + myd * 4) * 4u;  // byte offset
            const uint64_t v01 = pk2(v0, v1);
            const uint64_t v23 = pk2(v2, v3);
            asm volatile("st.shared.v2.u64 [%0], {%1, %2};"
                         :: "r"(hs_local + wb), "l"(v01), "l"(v23) : "memory");
            asm volatile("st.shared::cluster.u64 [%0], %1;"
                         :: "r"(hs_peer + wb),      "l"(v01) : "memory");
            asm volatile("st.shared::cluster.u64 [%0], %1;"
                         :: "r"(hs_peer + wb + 8u), "l"(v23) : "memory");

            if (t == T_ - 1) {
                out[(size_t)(b0 + 0) * K_ + myd] = v0;
                out[(size_t)(b0 + 1) * K_ + myd] = v1;
                out[(size_t)(b0 + 2) * K_ + myd] = v2;
                out[(size_t)(b0 + 3) * K_ + myd] = v3;
            }
        }

        // release own+peer writes; prefetch next step's xU under the barrier latency
        asm volatile("barrier.cluster.arrive.aligned;" ::: "memory");
        if (dh == 0 && t + 1 < T_) {
            const float* xp = xbase + (size_t)(t + 1) * K_;
            xu0 = xp[0];
            xu1 = xp[(size_t)1 * T_ * K_];
            xu2 = xp[(size_t)2 * T_ * K_];
            xu3 = xp[(size_t)3 * T_ * K_];
        }
        asm volatile("barrier.cluster.wait.aligned;" ::: "memory");
    }
}

// ---------------------------------------------------------------------------
extern "C" void kernel_launch(void* const* d_in, const int* in_sizes, int n_in,
                              void* d_out, int out_size) {
    const float* X    = (const float*)d_in[0];  // [B,T,D]
    const float* U    = (const float*)d_in[1];  // [D,K]
    const float* W    = (const float*)d_in[2];  // [K,K]
    const float* bias = (const float*)d_in[3];  // [K]
    float* out = (float*)d_out;                 // [B,1,K]

    // Phase A: xU = X @ U + b
    dim3 g1(BT_ / 128, K_ / 128);
    xu_gemm<<<g1, 256>>>(X, U, bias);

    // Phase B: persistent cluster recurrence
    rnn_scan<<<128, 256>>>(W, out);
}